// round 4
// baseline (speedup 1.0000x reference)
#include <cuda_runtime.h>
#include <cstdint>

// ---------------------------------------------------------------------------
// QLSTM fused persistent kernel.
//   * each gate uses only W[0,:]  -> theta is a scalar per batch element
//   * _expval(theta,U) = alpha + R*cos(theta - phi)   (3 consts per gate)
//   * f,i,g,o are scalars per row -> c[b,:], h[b,:] uniform over hidden dim
// One kernel, three concurrent roles synchronized by release/acquire counters:
//   block 0           : gate constants, then 128 independent scalar scans
//   blocks 1..PB      : projection z[t,b,g] = x[t,b,:] . Wg[0,:512]
//   blocks PB+1..G-1  : broadcast h/c scalars into the 67.6 MB output
// All blocks resident (grid = 2 x #SM, __launch_bounds__(256,2)) => polling safe.
// ---------------------------------------------------------------------------

#define T_STEPS 256
#define BATCH   128
#define ROWS    (T_STEPS * BATCH)   // 32768
#define DIMQ    256

__device__ float4   g_z[ROWS];      // per (t,b): x-projection per gate
__device__ float    g_h[ROWS];      // h scalar per (t,b)
__device__ float    g_cfin[BATCH];  // final c per b
__device__ unsigned g_cnt[T_STEPS]; // rows of z done per t (target 128)
__device__ unsigned g_prog[4];      // scan steps done per scan-warp (target 257)

struct Args {
    const float* x;
    const float* W[4];
    const float* b[4];
    const float* P[4];
    float4* out;
    int PB;   // number of proj blocks
    int Wp;   // number of proj warps (PB*8)
    int BB;   // number of bcast blocks
    int n4;   // out_size / 4
};

// ---------------- sync primitives ----------------
__device__ __forceinline__ void red_release(unsigned* p, unsigned v) {
    asm volatile("red.release.gpu.add.u32 [%0], %1;" :: "l"(p), "r"(v) : "memory");
}
__device__ __forceinline__ unsigned ld_rlx(const unsigned* p) {
    unsigned v;
    asm volatile("ld.relaxed.gpu.u32 %0, [%1];" : "=r"(v) : "l"(p) : "memory");
    return v;
}
__device__ __forceinline__ void fence_acq() {
    asm volatile("fence.acq_rel.gpu;" ::: "memory");
}

// ---------------- math helpers ----------------
__device__ __forceinline__ float2 cmul(float2 a, float2 b) {
    return make_float2(a.x * b.x - a.y * b.y, a.x * b.y + a.y * b.x);
}
// prefix-XOR from MSB = CNOT-chain permutation on 8-bit basis index
__device__ __forceinline__ int chain_perm(int k) {
    k ^= k >> 1; k ^= k >> 2; k ^= k >> 4;
    return k & 0xFF;
}
__device__ __forceinline__ float tanh_ex(float x) {
    float e = __expf(2.f * x);
    return 1.f - __fdividef(2.f, e + 1.f);
}

// ---------------- init (zero counters each replay) ----------------
__global__ void init_kernel() {
    int i = threadIdx.x;
    g_cnt[i] = 0u;
    if (i < 4) g_prog[i] = 0u;
}

// ---------------- fused kernel ----------------
__global__ void __launch_bounds__(256, 2) fused_kernel(Args a) {
    const int bid = blockIdx.x;
    const int tid = threadIdx.x;

    // shared only used by block 0 (consts phase); ~4.8 KB static
    __shared__ float2 rot[2][8][2][2];
    __shared__ float2 u0[DIMQ];
    __shared__ float2 u1[DIMQ];
    __shared__ float  rbuf[4][8];
    __shared__ float  s_gate[4][5];   // alpha, R, phi, sW, b0

    if (bid == 0) {
        // =================== gate constants (4 gates, sequential) ==========
        const int k   = tid;          // 0..255
        const int pk0 = chain_perm(k);
        const int lane = k & 31, warp = k >> 5;

        for (int g = 0; g < 4; ++g) {
            __syncthreads();   // protect smem reuse across gate iterations
            const float* P = a.P[g];
            if (k < 16) {
                int l = k >> 3, w = k & 7;
                float phi = P[(l * 8 + w) * 3 + 0];
                float th  = P[(l * 8 + w) * 3 + 1];
                float om  = P[(l * 8 + w) * 3 + 2];
                float s, c;
                sincosf(0.5f * th, &s, &c);
                float hp = 0.5f * (phi + om);
                float hm = 0.5f * (phi - om);
                float2 ep = make_float2(cosf(hp), -sinf(hp));
                float2 em = make_float2(cosf(hm),  sinf(hm));
                rot[l][w][0][0] = make_float2( ep.x * c,  ep.y * c);
                rot[l][w][0][1] = make_float2(-em.x * s, -em.y * s);
                rot[l][w][1][0] = make_float2( em.x * s, -em.y * s);
                rot[l][w][1][1] = make_float2( ep.x * c, -ep.y * c);
            }
            __syncthreads();

            // layer-1 columns (kron product)
            float2 a0v = make_float2(1.f, 0.f);
            float2 a1v = make_float2(1.f, 0.f);
            #pragma unroll
            for (int w = 0; w < 8; ++w) {
                int kb = (k >> (7 - w)) & 1;
                a0v = cmul(a0v, rot[0][w][kb][0]);
                a1v = cmul(a1v, rot[0][w][kb][(w == 0) ? 1 : 0]);
            }
            u0[pk0] = a0v;
            u1[pk0] = a1v;
            __syncthreads();

            // layer 2, one wire at a time
            #pragma unroll
            for (int w = 0; w < 8; ++w) {
                int p = 7 - w, m = 1 << p, kb = (k >> p) & 1;
                float2 x0 = u0[k & ~m], x1 = u0[k | m];
                float2 y0 = u1[k & ~m], y1 = u1[k | m];
                __syncthreads();
                float2 r0 = rot[1][w][kb][0];
                float2 r1 = rot[1][w][kb][1];
                u0[k] = make_float2(r0.x * x0.x - r0.y * x0.y + r1.x * x1.x - r1.y * x1.y,
                                    r0.x * x0.y + r0.y * x0.x + r1.x * x1.y + r1.y * x1.x);
                u1[k] = make_float2(r0.x * y0.x - r0.y * y0.y + r1.x * y1.x - r1.y * y1.y,
                                    r0.x * y0.y + r0.y * y0.x + r1.x * y1.y + r1.y * y1.x);
                __syncthreads();
            }

            // final CNOT-chain permutation
            float2 c0 = u0[k], c1 = u1[k];
            __syncthreads();
            u0[pk0] = c0; u1[pk0] = c1;
            __syncthreads();
            c0 = u0[k]; c1 = u1[k];

            float z0 = (k < 128) ? 1.f : -1.f;
            float A  = z0 * (c0.x * c0.x + c0.y * c0.y);
            float Bv = z0 * (c1.x * c1.x + c1.y * c1.y);
            float Cv = -2.f * z0 * (c0.y * c1.x - c0.x * c1.y);
            const float* W = a.W[g];
            float sw = W[512 + k] + W[768 + k];

            float vals[4] = {A, Bv, Cv, sw};
            #pragma unroll
            for (int i = 0; i < 4; ++i) {
                float xv = vals[i];
                #pragma unroll
                for (int off = 16; off; off >>= 1)
                    xv += __shfl_xor_sync(0xffffffffu, xv, off);
                if (lane == 0) rbuf[i][warp] = xv;
            }
            __syncthreads();
            if (k == 0) {
                float t[4];
                #pragma unroll
                for (int i = 0; i < 4; ++i) {
                    float s = 0.f;
                    #pragma unroll
                    for (int wv = 0; wv < 8; ++wv) s += rbuf[i][wv];
                    t[i] = s;
                }
                float alpha = 0.5f * (t[0] + t[1]);
                float beta  = 0.5f * (t[0] - t[1]);
                float gamma = 0.5f * t[2];
                float R     = sqrtf(beta * beta + gamma * gamma);
                float phi   = (R > 0.f) ? atan2f(gamma, beta) : 0.f;
                s_gate[g][0] = alpha;
                s_gate[g][1] = R;
                s_gate[g][2] = phi;
                s_gate[g][3] = t[3];
                s_gate[g][4] = a.b[g][0];
            }
        }
        __syncthreads();

        // =================== scalar scan (threads 0..127) ==================
        if (tid >= BATCH) return;
        const int b = tid, sw_ = b >> 5, slane = b & 31;

        const float af = s_gate[0][0], Rf = s_gate[0][1], swf = s_gate[0][3];
        const float ai = s_gate[1][0], Ri = s_gate[1][1], swi = s_gate[1][3];
        const float ag = s_gate[2][0], Rg = s_gate[2][1], swg = s_gate[2][3];
        const float ao = s_gate[3][0], Ro = s_gate[3][1], swo = s_gate[3][3];
        const float tbf = s_gate[0][4] - s_gate[0][2];
        const float tbi = s_gate[1][4] - s_gate[1][2];
        const float tbg = s_gate[2][4] - s_gate[2][2];
        const float tbo = s_gate[3][4] - s_gate[3][2];
        const float haf = 0.5f * af, hRf = 0.5f * Rf;
        const float hai = 0.5f * ai, hRi = 0.5f * Ri;
        const float hao = 0.5f * ao, hRo = 0.5f * Ro;

        float4 zb[4], zn[4];
        // wait group 0
        while (ld_rlx(&g_cnt[0]) < 128u || ld_rlx(&g_cnt[1]) < 128u ||
               ld_rlx(&g_cnt[2]) < 128u || ld_rlx(&g_cnt[3]) < 128u)
            __nanosleep(64);
        fence_acq();
        #pragma unroll
        for (int j = 0; j < 4; ++j) {
            float4 z = g_z[j * BATCH + b];
            zb[j] = make_float4(z.x + tbf, z.y + tbi, z.z + tbg, z.w + tbo);
        }

        float h = 0.f, cc = 0.f;
        #define QSTEP(ZV, T) { \
            float ff = 0.5f + 0.5f * tanh_ex(fmaf(hRf, __cosf(fmaf(h, swf, (ZV).x)), haf)); \
            float ii = 0.5f + 0.5f * tanh_ex(fmaf(hRi, __cosf(fmaf(h, swi, (ZV).y)), hai)); \
            float gg =               tanh_ex(fmaf(Rg,  __cosf(fmaf(h, swg, (ZV).z)), ag )); \
            float oo = 0.5f + 0.5f * tanh_ex(fmaf(hRo, __cosf(fmaf(h, swo, (ZV).w)), hao)); \
            cc = fmaf(ff, cc, ii * gg); \
            h  = oo * tanh_ex(cc); \
            g_h[(T) * BATCH + b] = h; }

        for (int t0 = 0; t0 < T_STEPS; t0 += 4) {
            const bool more = (t0 + 4 < T_STEPS);
            unsigned c0 = 128u, c1 = 128u, c2 = 128u, c3 = 128u;
            if (more) {   // early relaxed reads: latency hides under steps 0-1
                c0 = ld_rlx(&g_cnt[t0 + 4]); c1 = ld_rlx(&g_cnt[t0 + 5]);
                c2 = ld_rlx(&g_cnt[t0 + 6]); c3 = ld_rlx(&g_cnt[t0 + 7]);
            }
            QSTEP(zb[0], t0 + 0);
            QSTEP(zb[1], t0 + 1);
            if (more) {
                if ((c0 < 128u) | (c1 < 128u) | (c2 < 128u) | (c3 < 128u)) {
                    while (ld_rlx(&g_cnt[t0 + 4]) < 128u || ld_rlx(&g_cnt[t0 + 5]) < 128u ||
                           ld_rlx(&g_cnt[t0 + 6]) < 128u || ld_rlx(&g_cnt[t0 + 7]) < 128u)
                        __nanosleep(32);
                }
                fence_acq();
                #pragma unroll
                for (int j = 0; j < 4; ++j) {
                    float4 z = g_z[(t0 + 4 + j) * BATCH + b];
                    zn[j] = make_float4(z.x + tbf, z.y + tbi, z.z + tbg, z.w + tbo);
                }
            }
            QSTEP(zb[2], t0 + 2);
            QSTEP(zb[3], t0 + 3);
            __syncwarp();
            if (slane == 0) red_release(&g_prog[sw_], 4u);
            if (more) { zb[0] = zn[0]; zb[1] = zn[1]; zb[2] = zn[2]; zb[3] = zn[3]; }
        }
        #undef QSTEP
        g_cfin[b] = cc;
        __syncwarp();
        if (slane == 0) red_release(&g_prog[sw_], 1u);   // prog reaches 257
        return;
    }

    if (bid <= a.PB) {
        // =================== projection =====================================
        const int warp = tid >> 5, lane = tid & 31;
        const int gw = (bid - 1) * 8 + warp;
        const float4* x4 = reinterpret_cast<const float4*>(a.x);

        // weights in registers: 4 gates x 4 float4 per lane
        float4 wv0[4], wv1[4], wv2[4], wv3[4];
        {
            const float4* W0 = reinterpret_cast<const float4*>(a.W[0]);
            const float4* W1 = reinterpret_cast<const float4*>(a.W[1]);
            const float4* W2 = reinterpret_cast<const float4*>(a.W[2]);
            const float4* W3 = reinterpret_cast<const float4*>(a.W[3]);
            #pragma unroll
            for (int it = 0; it < 4; ++it) {
                int e4 = it * 32 + lane;
                wv0[it] = W0[e4]; wv1[it] = W1[e4];
                wv2[it] = W2[e4]; wv3[it] = W3[e4];
            }
        }

        for (int r = gw; r < ROWS; r += a.Wp) {
            const float4* xr = x4 + (size_t)r * 128;
            float s0 = 0.f, s1 = 0.f, s2 = 0.f, s3 = 0.f;
            #pragma unroll
            for (int it = 0; it < 4; ++it) {
                float4 xv = xr[it * 32 + lane];
                s0 = fmaf(xv.x, wv0[it].x, s0); s0 = fmaf(xv.y, wv0[it].y, s0);
                s0 = fmaf(xv.z, wv0[it].z, s0); s0 = fmaf(xv.w, wv0[it].w, s0);
                s1 = fmaf(xv.x, wv1[it].x, s1); s1 = fmaf(xv.y, wv1[it].y, s1);
                s1 = fmaf(xv.z, wv1[it].z, s1); s1 = fmaf(xv.w, wv1[it].w, s1);
                s2 = fmaf(xv.x, wv2[it].x, s2); s2 = fmaf(xv.y, wv2[it].y, s2);
                s2 = fmaf(xv.z, wv2[it].z, s2); s2 = fmaf(xv.w, wv2[it].w, s2);
                s3 = fmaf(xv.x, wv3[it].x, s3); s3 = fmaf(xv.y, wv3[it].y, s3);
                s3 = fmaf(xv.z, wv3[it].z, s3); s3 = fmaf(xv.w, wv3[it].w, s3);
            }
            #pragma unroll
            for (int off = 16; off; off >>= 1) {
                s0 += __shfl_xor_sync(0xffffffffu, s0, off);
                s1 += __shfl_xor_sync(0xffffffffu, s1, off);
                s2 += __shfl_xor_sync(0xffffffffu, s2, off);
                s3 += __shfl_xor_sync(0xffffffffu, s3, off);
            }
            if (lane == 0) {
                g_z[r] = make_float4(s0, s1, s2, s3);
                red_release(&g_cnt[r >> 7], 1u);
            }
        }
        return;
    }

    // =================== broadcast write ===================================
    {
        const int cb = bid - 1 - a.PB;
        const int chunk = (a.n4 + a.BB - 1) / a.BB;
        int start = cb * chunk;
        int end   = start + chunk;
        if (end > a.n4) end = a.n4;
        if (start >= end) return;

        const int lastrow = (end - 1) >> 7;   // 128 float4 per 512-float row
        unsigned req;
        if (lastrow < ROWS)              req = (unsigned)(lastrow >> 7) + 1u;
        else if (lastrow < ROWS + BATCH) req = 256u;
        else                             req = 257u;

        if (tid == 0) {
            while (ld_rlx(&g_prog[0]) < req || ld_rlx(&g_prog[1]) < req ||
                   ld_rlx(&g_prog[2]) < req || ld_rlx(&g_prog[3]) < req)
                __nanosleep(256);
            fence_acq();
        }
        __syncthreads();

        float4* out = a.out;
        for (int i = start + tid; i < end; i += 256) {
            int row = i >> 7;
            float v;
            if (row < ROWS)              v = g_h[row];
            else if (row < ROWS + BATCH) v = g_h[row - BATCH];     // h at t=255
            else                         v = g_cfin[row - ROWS - BATCH];
            out[i] = make_float4(v, v, v, v);
        }
    }
}

// ---------------- launch ----------------
extern "C" void kernel_launch(void* const* d_in, const int* in_sizes, int n_in,
                              void* d_out, int out_size) {
    static int s_sm = -1;
    if (s_sm < 0) {
        int dev = 0;
        cudaGetDevice(&dev);
        cudaDeviceGetAttribute(&s_sm, cudaDevAttrMultiProcessorCount, dev);
        if (s_sm <= 0) s_sm = 148;
    }
    const int G  = 2 * s_sm;           // all blocks resident (launch_bounds(256,2))
    int PB = (G - 1) * 55 / 100;       // proj share
    if (PB < 1) PB = 1;
    int BB = G - 1 - PB;
    if (BB < 1) { BB = 1; PB = G - 2; }

    Args a;
    a.x = (const float*)d_in[0];
    a.W[0] = (const float*)d_in[1];  a.b[0] = (const float*)d_in[2];  a.P[0] = (const float*)d_in[3];
    a.W[1] = (const float*)d_in[4];  a.b[1] = (const float*)d_in[5];  a.P[1] = (const float*)d_in[6];
    a.W[2] = (const float*)d_in[7];  a.b[2] = (const float*)d_in[8];  a.P[2] = (const float*)d_in[9];
    a.W[3] = (const float*)d_in[10]; a.b[3] = (const float*)d_in[11]; a.P[3] = (const float*)d_in[12];
    a.out = (float4*)d_out;
    a.PB = PB;
    a.Wp = PB * 8;
    a.BB = BB;
    a.n4 = out_size / 4;

    init_kernel<<<1, 256>>>();
    fused_kernel<<<G, 256>>>(a);
}